// round 1
// baseline (speedup 1.0000x reference)
#include <cuda_runtime.h>
#include <cuda_bf16.h>

// Problem constants
#define NUM_HEADS 8
#define NUM_G     50
#define NUM_ELEM  100

// offsets = linspace(0, 12, 50) -> spacing 12/49 ; std = 12/50
#define RBF_DELTA (12.0f / 49.0f)
#define RBF_COEFF (-8.680555555555555f)   // -0.5 / (0.24^2)

__global__ __launch_bounds__(256) void pair_embed_kernel(
    const int*   __restrict__ anum,
    const int*   __restrict__ edge_src,
    const int*   __restrict__ edge_dst,
    const float* __restrict__ dist,
    const float* __restrict__ emb,
    float*       __restrict__ out,
    int E)
{
    int tid  = blockIdx.x * blockDim.x + threadIdx.x;
    int eRaw = tid >> 3;        // edge id
    int h    = tid & 7;         // head id (sub-lane within 8-group)
    // Clamp so all lanes stay active for the shuffles (grid covers E*8 exactly
    // when E*8 % 256 == 0, but be safe for arbitrary E).
    int e = (eRaw < E) ? eRaw : (E - 1);

    float d  = __ldg(dist + e);
    int   s  = __ldg(edge_src + e);
    int   t  = __ldg(edge_dst + e);
    int   as = __ldg(anum + s);
    int   ad = __ldg(anum + t);

    // Each of the 8 lanes of this edge computes rbf[g] for g = h, h+8, h+16, ...
    float r[7];
#pragma unroll
    for (int k = 0; k < 7; k++) {
        int   g    = h + 8 * k;
        float diff = d - (float)g * RBF_DELTA;
        float v    = __expf(RBF_COEFF * diff * diff);
        r[k] = (g < NUM_G) ? v : 0.0f;
    }

    // embedding[as][ad][0][h][:] : contiguous 50 floats, 8-byte aligned
    const float2* ep = (const float2*)(emb
        + ((size_t)as * NUM_ELEM + (size_t)ad) * (NUM_HEADS * NUM_G)
        + h * NUM_G);

    float acc0 = 0.0f, acc1 = 0.0f;
#pragma unroll
    for (int j = 0; j < NUM_G / 2; j++) {
        float2 w  = __ldg(ep + j);
        int    g0 = 2 * j;
        int    g1 = 2 * j + 1;
        // fetch rbf[g] from the owning lane within the 8-lane group
        float r0 = __shfl_sync(0xffffffffu, r[g0 >> 3], g0 & 7, 8);
        float r1 = __shfl_sync(0xffffffffu, r[g1 >> 3], g1 & 7, 8);
        acc0 = fmaf(w.x, r0, acc0);
        acc1 = fmaf(w.y, r1, acc1);
    }

    if (eRaw < E)
        out[(size_t)eRaw * NUM_HEADS + h] = acc0 + acc1;
}

extern "C" void kernel_launch(void* const* d_in, const int* in_sizes, int n_in,
                              void* d_out, int out_size)
{
    const int*   anum = (const int*)d_in[0];
    const int*   eidx = (const int*)d_in[1];   // [2, E]
    const float* dist = (const float*)d_in[2];
    const float* emb  = (const float*)d_in[3];
    float*       out  = (float*)d_out;

    int E = in_sizes[2];                       // dist has E elements

    int threads = 256;
    long long total = (long long)E * NUM_HEADS;
    int blocks = (int)((total + threads - 1) / threads);

    pair_embed_kernel<<<blocks, threads>>>(anum, eidx, eidx + E, dist, emb, out, E);
}

// round 2
// speedup vs baseline: 2.7937x; 2.7937x over previous
#include <cuda_runtime.h>
#include <cuda_bf16.h>

// Problem constants
#define NUM_HEADS 8
#define NUM_G     50
#define NUM_ELEM  100
#define NB        (NUM_ELEM * NUM_ELEM)   // 10000 distinct (src,dst) pairs
#define E_MAX     1000000

// offsets = linspace(0, 12, 50) -> spacing 12/49 ; std = 12/50
#define RBF_DELTA (12.0f / 49.0f)
#define RBF_COEFF (-8.680555555555555f)   // -0.5 / (0.24^2)

// Scratch (no allocations allowed) -----------------------------------------
__device__ int g_hist[NB];
__device__ int g_off[NB];
__device__ int g_cur[NB];
__device__ int g_keys[E_MAX];
__device__ int g_sorted[E_MAX];

// K0: zero the histogram (must happen every launch for graph replay) -------
__global__ void k_zero()
{
    int i = blockIdx.x * blockDim.x + threadIdx.x;
    if (i < NB) g_hist[i] = 0;
}

// K1: compute pair key per edge + histogram ---------------------------------
__global__ __launch_bounds__(256) void k_key(
    const int* __restrict__ anum,
    const int* __restrict__ esrc,
    const int* __restrict__ edst,
    int E)
{
    int stride = gridDim.x * blockDim.x;
    for (int e = blockIdx.x * blockDim.x + threadIdx.x; e < E; e += stride) {
        int k = __ldg(anum + __ldg(esrc + e)) * NUM_ELEM
              + __ldg(anum + __ldg(edst + e));
        g_keys[e] = k;
        atomicAdd(&g_hist[k], 1);
    }
}

// K2: exclusive scan of 10000 bins (single block) ---------------------------
__global__ __launch_bounds__(1024) void k_scan()
{
    __shared__ int part[1024];
    const int CHUNK = (NB + 1023) / 1024;       // 10
    int t = threadIdx.x;
    int base = t * CHUNK;

    int s = 0;
    for (int k = 0; k < CHUNK; k++) {
        int i = base + k;
        if (i < NB) s += g_hist[i];
    }
    part[t] = s;
    __syncthreads();

    // Hillis-Steele inclusive scan over 1024 partials
    for (int d = 1; d < 1024; d <<= 1) {
        int v = (t >= d) ? part[t - d] : 0;
        __syncthreads();
        part[t] += v;
        __syncthreads();
    }

    int run = part[t] - s;                      // exclusive prefix for chunk
    for (int k = 0; k < CHUNK; k++) {
        int i = base + k;
        if (i < NB) {
            g_off[i] = run;
            g_cur[i] = run;
            run += g_hist[i];
        }
    }
}

// K3: scatter edge ids into pair-sorted order --------------------------------
__global__ __launch_bounds__(256) void k_scatter(int E)
{
    int stride = gridDim.x * blockDim.x;
    for (int e = blockIdx.x * blockDim.x + threadIdx.x; e < E; e += stride) {
        int p = atomicAdd(&g_cur[g_keys[e]], 1);
        g_sorted[p] = e;
    }
}

// K4: one block per pair; weights in smem (broadcast LDS), edges streamed ----
__global__ __launch_bounds__(128) void k_compute(
    const float* __restrict__ dist,
    const float* __restrict__ emb,
    float*       __restrict__ out)
{
    int b = blockIdx.x;                          // pair key
    __shared__ __align__(16) float Ws[NUM_HEADS * 52];  // 52-pad: 208B rows, 16B aligned

    const float* W = emb + (size_t)b * (NUM_HEADS * NUM_G);
    for (int i = threadIdx.x; i < NUM_HEADS * NUM_G; i += 128)
        Ws[(i / NUM_G) * 52 + (i % NUM_G)] = __ldg(W + i);
    __syncthreads();

    int cnt = g_hist[b];
    if (cnt == 0) return;
    int off = g_off[b];

    for (int i = threadIdx.x; i < cnt; i += 128) {
        int   e = g_sorted[off + i];
        float d = __ldg(dist + e);

        float rbf[NUM_G];
#pragma unroll
        for (int g = 0; g < NUM_G; g++) {
            float diff = d - (float)g * RBF_DELTA;
            rbf[g] = __expf(RBF_COEFF * diff * diff);
        }

        float acc[NUM_HEADS];
#pragma unroll
        for (int h = 0; h < NUM_HEADS; h++) {
            float a0 = 0.f, a1 = 0.f, a2 = 0.f, a3 = 0.f;
#pragma unroll
            for (int j = 0; j < 12; j++) {      // 48 of 50
                float4 w = *(const float4*)&Ws[h * 52 + 4 * j];
                a0 = fmaf(w.x, rbf[4 * j + 0], a0);
                a1 = fmaf(w.y, rbf[4 * j + 1], a1);
                a2 = fmaf(w.z, rbf[4 * j + 2], a2);
                a3 = fmaf(w.w, rbf[4 * j + 3], a3);
            }
            float2 w2 = *(const float2*)&Ws[h * 52 + 48];
            a0 = fmaf(w2.x, rbf[48], a0);
            a1 = fmaf(w2.y, rbf[49], a1);
            acc[h] = (a0 + a2) + (a1 + a3);
        }

        float4* o = (float4*)(out + (size_t)e * NUM_HEADS);
        o[0] = make_float4(acc[0], acc[1], acc[2], acc[3]);
        o[1] = make_float4(acc[4], acc[5], acc[6], acc[7]);
    }
}

extern "C" void kernel_launch(void* const* d_in, const int* in_sizes, int n_in,
                              void* d_out, int out_size)
{
    const int*   anum = (const int*)d_in[0];
    const int*   eidx = (const int*)d_in[1];   // [2, E]
    const float* dist = (const float*)d_in[2];
    const float* emb  = (const float*)d_in[3];
    float*       out  = (float*)d_out;

    int E = in_sizes[2];                       // dist has E elements
    if (E > E_MAX) E = E_MAX;

    k_zero<<<(NB + 255) / 256, 256>>>();
    k_key<<<2048, 256>>>(anum, eidx, eidx + E, E);
    k_scan<<<1, 1024>>>();
    k_scatter<<<2048, 256>>>(E);
    k_compute<<<NB, 128>>>(dist, emb, out);
}

// round 3
// speedup vs baseline: 2.9032x; 1.0392x over previous
#include <cuda_runtime.h>
#include <cuda_bf16.h>

// Problem constants
#define NUM_HEADS 8
#define NUM_G     50
#define NUM_ELEM  100
#define NB        (NUM_ELEM * NUM_ELEM)   // 10000 distinct (src,dst) pairs
#define E_MAX     1000000

// offsets = linspace(0, 12, 50) -> spacing 12/49 ; std = 12/50
#define RBF_DELTA (12.0f / 49.0f)
// -0.5/std^2 folded with log2(e) so exp() becomes a single ex2.approx
#define RBF_C2    (-8.680555555555555f * 1.4426950408889634f)

// ---- f32x2 packed helpers (sm_100+ PTX) -----------------------------------
__device__ __forceinline__ unsigned long long pk2(float x, float y) {
    unsigned long long r;
    asm("mov.b64 %0, {%1, %2};" : "=l"(r) : "f"(x), "f"(y));
    return r;
}
__device__ __forceinline__ void upk2(unsigned long long v, float& x, float& y) {
    asm("mov.b64 {%0, %1}, %2;" : "=f"(x), "=f"(y) : "l"(v));
}
__device__ __forceinline__ unsigned long long add2(unsigned long long a, unsigned long long b) {
    unsigned long long d;
    asm("add.rn.f32x2 %0, %1, %2;" : "=l"(d) : "l"(a), "l"(b));
    return d;
}
__device__ __forceinline__ unsigned long long mul2(unsigned long long a, unsigned long long b) {
    unsigned long long d;
    asm("mul.rn.f32x2 %0, %1, %2;" : "=l"(d) : "l"(a), "l"(b));
    return d;
}
__device__ __forceinline__ unsigned long long fma2(unsigned long long a, unsigned long long b,
                                                   unsigned long long c) {
    unsigned long long d;
    asm("fma.rn.f32x2 %0, %1, %2, %3;" : "=l"(d) : "l"(a), "l"(b), "l"(c));
    return d;
}
__device__ __forceinline__ float ex2(float x) {
    float r;
    asm("ex2.approx.f32 %0, %1;" : "=f"(r) : "f"(x));
    return r;
}

// Scratch (no allocations allowed) -------------------------------------------
__device__ int g_hist[NB];
__device__ int g_off[NB];
__device__ int g_cur[NB];
__device__ int g_keys[E_MAX];
__device__ int g_sorted[E_MAX];

// K0: zero the histogram (must happen every launch for graph replay) ----------
__global__ void k_zero()
{
    int i = blockIdx.x * blockDim.x + threadIdx.x;
    if (i < NB) g_hist[i] = 0;
}

// K1: pair key per edge + histogram (4 independent chains/thread for MLP) -----
__global__ __launch_bounds__(256) void k_key(
    const int* __restrict__ anum,
    const int* __restrict__ esrc,
    const int* __restrict__ edst,
    int E)
{
    const int S   = gridDim.x * blockDim.x;
    const int idx = blockIdx.x * blockDim.x + threadIdx.x;

    int kk[4];
#pragma unroll
    for (int u = 0; u < 4; u++) {
        int e = idx + u * S;
        if (e < E) {
            int k = __ldg(anum + __ldg(esrc + e)) * NUM_ELEM
                  + __ldg(anum + __ldg(edst + e));
            kk[u] = k;
            g_keys[e] = k;
        }
    }
#pragma unroll
    for (int u = 0; u < 4; u++) {
        int e = idx + u * S;
        if (e < E) atomicAdd(&g_hist[kk[u]], 1);
    }
}

// K2: exclusive scan of 10000 bins (single block) ------------------------------
__global__ __launch_bounds__(1024) void k_scan()
{
    __shared__ int part[1024];
    const int CHUNK = (NB + 1023) / 1024;       // 10
    int t = threadIdx.x;
    int base = t * CHUNK;

    int s = 0;
    for (int k = 0; k < CHUNK; k++) {
        int i = base + k;
        if (i < NB) s += g_hist[i];
    }
    part[t] = s;
    __syncthreads();

    for (int d = 1; d < 1024; d <<= 1) {
        int v = (t >= d) ? part[t - d] : 0;
        __syncthreads();
        part[t] += v;
        __syncthreads();
    }

    int run = part[t] - s;
    for (int k = 0; k < CHUNK; k++) {
        int i = base + k;
        if (i < NB) {
            g_off[i] = run;
            g_cur[i] = run;
            run += g_hist[i];
        }
    }
}

// K3: scatter edge ids into pair-sorted order (MLP=4) --------------------------
__global__ __launch_bounds__(256) void k_scatter(int E)
{
    const int S   = gridDim.x * blockDim.x;
    const int idx = blockIdx.x * blockDim.x + threadIdx.x;

    int kk[4];
#pragma unroll
    for (int u = 0; u < 4; u++) {
        int e = idx + u * S;
        if (e < E) kk[u] = g_keys[e];
    }
#pragma unroll
    for (int u = 0; u < 4; u++) {
        int e = idx + u * S;
        if (e < E) {
            int p = atomicAdd(&g_cur[kk[u]], 1);
            g_sorted[p] = e;
        }
    }
}

// K4: one block per pair; smem weights; f32x2 packed dot ------------------------
__global__ __launch_bounds__(128) void k_compute(
    const float* __restrict__ dist,
    const float* __restrict__ emb,
    float*       __restrict__ out)
{
    int b = blockIdx.x;                              // pair key
    int cnt = g_hist[b];
    if (cnt == 0) return;
    int off = g_off[b];

    // 52-float padded rows: 208 B each, 16B-aligned chunks for ulonglong2 loads
    __shared__ __align__(16) float Ws[NUM_HEADS * 52];
    const float* W = emb + (size_t)b * (NUM_HEADS * NUM_G);
    for (int i = threadIdx.x; i < NUM_HEADS * NUM_G; i += 128)
        Ws[(i / NUM_G) * 52 + (i % NUM_G)] = __ldg(W + i);
    __syncthreads();

    for (int i = threadIdx.x; i < cnt; i += 128) {
        int   e = g_sorted[off + i];
        float d = __ldg(dist + e);

        // rbf pairs: r2[j] = { exp2(C2*(d-g0*D)^2), exp2(C2*(d-g1*D)^2) }
        const unsigned long long d2 = pk2(d, d);
        const unsigned long long c2 = pk2(RBF_C2, RBF_C2);
        unsigned long long r2[NUM_G / 2];
#pragma unroll
        for (int j = 0; j < NUM_G / 2; j++) {
            unsigned long long noff = pk2(-(float)(2 * j) * RBF_DELTA,
                                          -(float)(2 * j + 1) * RBF_DELTA);
            unsigned long long diff = add2(d2, noff);
            unsigned long long arg  = mul2(mul2(diff, diff), c2);
            float a0, a1;
            upk2(arg, a0, a1);
            r2[j] = pk2(ex2(a0), ex2(a1));
        }

        float acc[NUM_HEADS];
#pragma unroll
        for (int h = 0; h < NUM_HEADS; h++) {
            unsigned long long accA = 0, accB = 0;   // {0.f,0.f}
#pragma unroll
            for (int j = 0; j < 12; j++) {           // gaussians 0..47
                ulonglong2 w = *(const ulonglong2*)&Ws[h * 52 + 4 * j];
                accA = fma2(w.x, r2[2 * j],     accA);
                accB = fma2(w.y, r2[2 * j + 1], accB);
            }
            {                                        // gaussians 48,49
                unsigned long long w = *(const unsigned long long*)&Ws[h * 52 + 48];
                accA = fma2(w, r2[24], accA);
            }
            float x0, x1, y0, y1;
            upk2(accA, x0, x1);
            upk2(accB, y0, y1);
            acc[h] = (x0 + y0) + (x1 + y1);
        }

        float4* o = (float4*)(out + (size_t)e * NUM_HEADS);
        o[0] = make_float4(acc[0], acc[1], acc[2], acc[3]);
        o[1] = make_float4(acc[4], acc[5], acc[6], acc[7]);
    }
}

extern "C" void kernel_launch(void* const* d_in, const int* in_sizes, int n_in,
                              void* d_out, int out_size)
{
    const int*   anum = (const int*)d_in[0];
    const int*   eidx = (const int*)d_in[1];   // [2, E]
    const float* dist = (const float*)d_in[2];
    const float* emb  = (const float*)d_in[3];
    float*       out  = (float*)d_out;

    int E = in_sizes[2];                       // dist has E elements
    if (E > E_MAX) E = E_MAX;

    k_zero<<<(NB + 255) / 256, 256>>>();
    k_key<<<1024, 256>>>(anum, eidx, eidx + E, E);
    k_scan<<<1, 1024>>>();
    k_scatter<<<1024, 256>>>(E);
    k_compute<<<NB, 128>>>(dist, emb, out);
}

// round 4
// speedup vs baseline: 3.3423x; 1.1512x over previous
#include <cuda_runtime.h>
#include <cuda_bf16.h>

// Problem constants
#define NUM_HEADS 8
#define NUM_G     50
#define NUM_ELEM  100
#define NB        (NUM_ELEM * NUM_ELEM)   // 10000 distinct (src,dst) pairs
#define E_MAX     1000000

// offsets = linspace(0, 12, 50) -> spacing 12/49 ; std = 12/50
#define RBF_DELTA (12.0f / 49.0f)
// -0.5/std^2 folded with log2(e) so exp() becomes a single ex2.approx
#define RBF_C2    (-8.680555555555555f * 1.4426950408889634f)

// ---- f32x2 packed helpers (sm_100+ PTX) -----------------------------------
__device__ __forceinline__ unsigned long long pk2(float x, float y) {
    unsigned long long r;
    asm("mov.b64 %0, {%1, %2};" : "=l"(r) : "f"(x), "f"(y));
    return r;
}
__device__ __forceinline__ void upk2(unsigned long long v, float& x, float& y) {
    asm("mov.b64 {%0, %1}, %2;" : "=f"(x), "=f"(y) : "l"(v));
}
__device__ __forceinline__ unsigned long long add2(unsigned long long a, unsigned long long b) {
    unsigned long long d;
    asm("add.rn.f32x2 %0, %1, %2;" : "=l"(d) : "l"(a), "l"(b));
    return d;
}
__device__ __forceinline__ unsigned long long mul2(unsigned long long a, unsigned long long b) {
    unsigned long long d;
    asm("mul.rn.f32x2 %0, %1, %2;" : "=l"(d) : "l"(a), "l"(b));
    return d;
}
__device__ __forceinline__ unsigned long long fma2(unsigned long long a, unsigned long long b,
                                                   unsigned long long c) {
    unsigned long long d;
    asm("fma.rn.f32x2 %0, %1, %2, %3;" : "=l"(d) : "l"(a), "l"(b), "l"(c));
    return d;
}
__device__ __forceinline__ float ex2(float x) {
    float r;
    asm("ex2.approx.f32 %0, %1;" : "=f"(r) : "f"(x));
    return r;
}

// Scratch (no allocations allowed) -------------------------------------------
// g_hist starts zeroed (device global) and is re-zeroed by k_scan each launch.
__device__ int g_hist[NB];
__device__ int g_off[NB + 1];
__device__ int g_packed[E_MAX];    // (pos_in_bin << 14) | key
__device__ int g_sorted[E_MAX];

// K1: key + in-bin rank per edge (the ONLY atomic pass) -----------------------
__global__ __launch_bounds__(256) void k_key(
    const int* __restrict__ anum,
    const int* __restrict__ esrc,
    const int* __restrict__ edst,
    int E)
{
    const int S   = gridDim.x * blockDim.x;
    const int idx = blockIdx.x * blockDim.x + threadIdx.x;

#pragma unroll
    for (int u = 0; u < 2; u++) {
        int e = idx + u * S;
        if (e < E) {
            int k = __ldg(anum + __ldg(esrc + e)) * NUM_ELEM
                  + __ldg(anum + __ldg(edst + e));
            int pos = atomicAdd(&g_hist[k], 1);
            g_packed[e] = (pos << 14) | k;
        }
    }
}

// K2: exclusive scan of 10000 bins (single block), then re-zero g_hist --------
__global__ __launch_bounds__(1024) void k_scan()
{
    __shared__ int part[1024];
    const int CHUNK = (NB + 1023) / 1024;       // 10
    int t = threadIdx.x;
    int base = t * CHUNK;

    int cnts[CHUNK];
    int s = 0;
#pragma unroll
    for (int k = 0; k < CHUNK; k++) {
        int i = base + k;
        cnts[k] = (i < NB) ? g_hist[i] : 0;
        s += cnts[k];
    }
    part[t] = s;
    __syncthreads();

    for (int d = 1; d < 1024; d <<= 1) {
        int v = (t >= d) ? part[t - d] : 0;
        __syncthreads();
        part[t] += v;
        __syncthreads();
    }

    int run = part[t] - s;                      // exclusive prefix for chunk
#pragma unroll
    for (int k = 0; k < CHUNK; k++) {
        int i = base + k;
        if (i < NB) {
            g_off[i] = run;
            run += cnts[k];
            g_hist[i] = 0;                      // ready for next launch/replay
        }
    }
    if (t == 1023) g_off[NB] = part[1023];      // total = E
}

// K3: atomic-free scatter into pair-sorted order -------------------------------
__global__ __launch_bounds__(256) void k_scatter(int E)
{
    const int S   = gridDim.x * blockDim.x;
    const int idx = blockIdx.x * blockDim.x + threadIdx.x;

#pragma unroll
    for (int u = 0; u < 2; u++) {
        int e = idx + u * S;
        if (e < E) {
            int p   = g_packed[e];
            int k   = p & (NB + 6383);          // low 14 bits (16383 mask)
            int pos = p >> 14;
            g_sorted[g_off[k & 16383] + pos] = e;
        }
    }
}

// K4: one block per pair; smem weights; f32x2 packed dot ------------------------
__global__ __launch_bounds__(128) void k_compute(
    const float* __restrict__ dist,
    const float* __restrict__ emb,
    float*       __restrict__ out)
{
    int b   = blockIdx.x;                        // pair key
    int off = g_off[b];
    int cnt = g_off[b + 1] - off;
    if (cnt == 0) return;

    // 52-float padded rows: 208 B each, 16B-aligned chunks for ulonglong2 loads
    __shared__ __align__(16) float Ws[NUM_HEADS * 52];
    const float* W = emb + (size_t)b * (NUM_HEADS * NUM_G);
    for (int i = threadIdx.x; i < NUM_HEADS * NUM_G; i += 128)
        Ws[(i / NUM_G) * 52 + (i % NUM_G)] = __ldg(W + i);
    __syncthreads();

    for (int i = threadIdx.x; i < cnt; i += 128) {
        int   e = g_sorted[off + i];
        float d = __ldg(dist + e);

        // rbf pairs: r2[j] = { exp2(C2*(d-g0*D)^2), exp2(C2*(d-g1*D)^2) }
        const unsigned long long d2 = pk2(d, d);
        const unsigned long long c2 = pk2(RBF_C2, RBF_C2);
        unsigned long long r2[NUM_G / 2];
#pragma unroll
        for (int j = 0; j < NUM_G / 2; j++) {
            unsigned long long noff = pk2(-(float)(2 * j) * RBF_DELTA,
                                          -(float)(2 * j + 1) * RBF_DELTA);
            unsigned long long diff = add2(d2, noff);
            unsigned long long arg  = mul2(mul2(diff, diff), c2);
            float a0, a1;
            upk2(arg, a0, a1);
            r2[j] = pk2(ex2(a0), ex2(a1));
        }

        float acc[NUM_HEADS];
#pragma unroll
        for (int h = 0; h < NUM_HEADS; h++) {
            unsigned long long accA = 0, accB = 0;   // {0.f,0.f}
#pragma unroll
            for (int j = 0; j < 12; j++) {           // gaussians 0..47
                ulonglong2 w = *(const ulonglong2*)&Ws[h * 52 + 4 * j];
                accA = fma2(w.x, r2[2 * j],     accA);
                accB = fma2(w.y, r2[2 * j + 1], accB);
            }
            {                                        // gaussians 48,49
                unsigned long long w = *(const unsigned long long*)&Ws[h * 52 + 48];
                accA = fma2(w, r2[24], accA);
            }
            float x0, x1, y0, y1;
            upk2(accA, x0, x1);
            upk2(accB, y0, y1);
            acc[h] = (x0 + y0) + (x1 + y1);
        }

        float4* o = (float4*)(out + (size_t)e * NUM_HEADS);
        o[0] = make_float4(acc[0], acc[1], acc[2], acc[3]);
        o[1] = make_float4(acc[4], acc[5], acc[6], acc[7]);
    }
}

extern "C" void kernel_launch(void* const* d_in, const int* in_sizes, int n_in,
                              void* d_out, int out_size)
{
    const int*   anum = (const int*)d_in[0];
    const int*   eidx = (const int*)d_in[1];   // [2, E]
    const float* dist = (const float*)d_in[2];
    const float* emb  = (const float*)d_in[3];
    float*       out  = (float*)d_out;

    int E = in_sizes[2];                       // dist has E elements
    if (E > E_MAX) E = E_MAX;

    k_key<<<2048, 256>>>(anum, eidx, eidx + E, E);
    k_scan<<<1, 1024>>>();
    k_scatter<<<2048, 256>>>(E);
    k_compute<<<NB, 128>>>(dist, emb, out);
}

// round 5
// speedup vs baseline: 4.1047x; 1.2281x over previous
#include <cuda_runtime.h>
#include <cuda_bf16.h>

// Problem constants
#define NUM_HEADS 8
#define NUM_G     50
#define NUM_ELEM  100
#define NB        (NUM_ELEM * NUM_ELEM)   // 10000 distinct (src,dst) pairs
#define E_MAX     1000000

// offsets = linspace(0, 12, 50) -> spacing 12/49 ; std = 12/50
#define RBF_DELTA (12.0 / 49.0)
// k = -0.5/std^2 * log2(e)  (so exp() becomes ex2.approx)
#define RBF_K     (-8.680555555555555 * 1.4426950408889634)
// arg(g) = K*d^2 + MSLOPE*g*d + CQUAD*g^2
#define MSLOPE    (-2.0 * RBF_K * RBF_DELTA)
#define CQUAD     (RBF_K * RBF_DELTA * RBF_DELTA)

// ---- f32x2 packed helpers (sm_100+ PTX) -----------------------------------
__device__ __forceinline__ unsigned long long pk2(float x, float y) {
    unsigned long long r;
    asm("mov.b64 %0, {%1, %2};" : "=l"(r) : "f"(x), "f"(y));
    return r;
}
__device__ __forceinline__ void upk2(unsigned long long v, float& x, float& y) {
    asm("mov.b64 {%0, %1}, %2;" : "=f"(x), "=f"(y) : "l"(v));
}
__device__ __forceinline__ unsigned long long add2(unsigned long long a, unsigned long long b) {
    unsigned long long d;
    asm("add.rn.f32x2 %0, %1, %2;" : "=l"(d) : "l"(a), "l"(b));
    return d;
}
__device__ __forceinline__ unsigned long long fma2(unsigned long long a, unsigned long long b,
                                                   unsigned long long c) {
    unsigned long long d;
    asm("fma.rn.f32x2 %0, %1, %2, %3;" : "=l"(d) : "l"(a), "l"(b), "l"(c));
    return d;
}
__device__ __forceinline__ float ex2(float x) {
    float r;
    asm("ex2.approx.f32 %0, %1;" : "=f"(r) : "f"(x));
    return r;
}

// Scratch (no allocations allowed) -------------------------------------------
// g_hist starts zeroed (device global) and is re-zeroed by k_scan each launch.
__device__ int  g_hist[NB];
__device__ int  g_off[NB + 1];
__device__ int  g_packed[E_MAX];     // (pos_in_bin << 14) | key
__device__ int2 g_sorted2[E_MAX];    // {edge_id, dist_bits} in pair-sorted order

// K1: key + in-bin rank per edge (the ONLY atomic pass) -----------------------
__global__ __launch_bounds__(256) void k_key(
    const int* __restrict__ anum,
    const int* __restrict__ esrc,
    const int* __restrict__ edst,
    int E)
{
    const int S   = gridDim.x * blockDim.x;
    const int idx = blockIdx.x * blockDim.x + threadIdx.x;

#pragma unroll
    for (int u = 0; u < 2; u++) {
        int e = idx + u * S;
        if (e < E) {
            int k = __ldg(anum + __ldg(esrc + e)) * NUM_ELEM
                  + __ldg(anum + __ldg(edst + e));
            int pos = atomicAdd(&g_hist[k], 1);
            g_packed[e] = (pos << 14) | k;
        }
    }
}

// K2: exclusive scan of 10000 bins (single block), then re-zero g_hist --------
__global__ __launch_bounds__(1024) void k_scan()
{
    __shared__ int part[1024];
    const int CHUNK = (NB + 1023) / 1024;       // 10
    int t = threadIdx.x;
    int base = t * CHUNK;

    int cnts[CHUNK];
    int s = 0;
#pragma unroll
    for (int k = 0; k < CHUNK; k++) {
        int i = base + k;
        cnts[k] = (i < NB) ? g_hist[i] : 0;
        s += cnts[k];
    }
    part[t] = s;
    __syncthreads();

    for (int d = 1; d < 1024; d <<= 1) {
        int v = (t >= d) ? part[t - d] : 0;
        __syncthreads();
        part[t] += v;
        __syncthreads();
    }

    int run = part[t] - s;                      // exclusive prefix for chunk
#pragma unroll
    for (int k = 0; k < CHUNK; k++) {
        int i = base + k;
        if (i < NB) {
            g_off[i] = run;
            run += cnts[k];
            g_hist[i] = 0;                      // ready for next launch/replay
        }
    }
    if (t == 1023) g_off[NB] = part[1023];      // total = E
}

// K3: atomic-free scatter of {edge, dist} into pair-sorted order ---------------
__global__ __launch_bounds__(256) void k_scatter(const float* __restrict__ dist, int E)
{
    const int S   = gridDim.x * blockDim.x;
    const int idx = blockIdx.x * blockDim.x + threadIdx.x;

#pragma unroll
    for (int u = 0; u < 2; u++) {
        int e = idx + u * S;
        if (e < E) {
            int p   = g_packed[e];
            int k   = p & 16383;
            int pos = p >> 14;
            g_sorted2[g_off[k] + pos] = make_int2(e, __float_as_int(__ldg(dist + e)));
        }
    }
}

// K4: one block per pair; j-outer/h-inner dot keeps regs low -------------------
__global__ __launch_bounds__(128, 12) void k_compute(
    const float* __restrict__ emb,
    float*       __restrict__ out)
{
    int b   = blockIdx.x;                        // pair key
    int off = g_off[b];
    int cnt = g_off[b + 1] - off;
    if (cnt == 0) return;

    // Ws2[j][h] = { w[h][2j], w[h][2j+1] } : 25 x 8 u64 = 1600 B
    __shared__ __align__(16) unsigned long long Ws2[25 * 8];
    const unsigned long long* W64 =
        (const unsigned long long*)(emb + (size_t)b * (NUM_HEADS * NUM_G));
    for (int i = threadIdx.x; i < 25 * NUM_HEADS; i += 128) {
        int h = i / 25, j = i % 25;              // source u64 index = h*25+j (coalesced)
        Ws2[j * 8 + h] = __ldg(W64 + i);
    }
    __syncthreads();

    for (int i = threadIdx.x; i < cnt; i += 128) {
        int2  pe = __ldg(&g_sorted2[off + i]);
        int   e  = pe.x;
        float d  = __int_as_float(pe.y);

        const unsigned long long d2 = pk2(d, d);
        const float t = (float)RBF_K * d * d;    // shared quadratic term
        const unsigned long long t2 = pk2(t, t);

        unsigned long long acc2[NUM_HEADS];
#pragma unroll
        for (int h = 0; h < NUM_HEADS; h++) acc2[h] = 0ull;

#pragma unroll
        for (int j = 0; j < NUM_G / 2; j++) {
            const float g0 = (float)(2 * j), g1 = (float)(2 * j + 1);
            // arg(g) = t + MSLOPE*g*d + CQUAD*g^2   (constants fold at compile time)
            unsigned long long m2 = pk2((float)(MSLOPE * g0), (float)(MSLOPE * g1));
            unsigned long long q2 = pk2((float)(CQUAD * g0 * g0), (float)(CQUAD * g1 * g1));
            unsigned long long arg = fma2(m2, d2, add2(t2, q2));
            float a0, a1;
            upk2(arg, a0, a1);
            unsigned long long r2 = pk2(ex2(a0), ex2(a1));

            const ulonglong2* wrow = (const ulonglong2*)&Ws2[j * 8];
            ulonglong2 w01 = wrow[0];
            ulonglong2 w23 = wrow[1];
            ulonglong2 w45 = wrow[2];
            ulonglong2 w67 = wrow[3];
            acc2[0] = fma2(w01.x, r2, acc2[0]);
            acc2[1] = fma2(w01.y, r2, acc2[1]);
            acc2[2] = fma2(w23.x, r2, acc2[2]);
            acc2[3] = fma2(w23.y, r2, acc2[3]);
            acc2[4] = fma2(w45.x, r2, acc2[4]);
            acc2[5] = fma2(w45.y, r2, acc2[5]);
            acc2[6] = fma2(w67.x, r2, acc2[6]);
            acc2[7] = fma2(w67.y, r2, acc2[7]);
        }

        float acc[NUM_HEADS];
#pragma unroll
        for (int h = 0; h < NUM_HEADS; h++) {
            float x0, x1;
            upk2(acc2[h], x0, x1);
            acc[h] = x0 + x1;
        }

        float4* o = (float4*)(out + (size_t)e * NUM_HEADS);
        o[0] = make_float4(acc[0], acc[1], acc[2], acc[3]);
        o[1] = make_float4(acc[4], acc[5], acc[6], acc[7]);
    }
}

extern "C" void kernel_launch(void* const* d_in, const int* in_sizes, int n_in,
                              void* d_out, int out_size)
{
    const int*   anum = (const int*)d_in[0];
    const int*   eidx = (const int*)d_in[1];   // [2, E]
    const float* dist = (const float*)d_in[2];
    const float* emb  = (const float*)d_in[3];
    float*       out  = (float*)d_out;

    int E = in_sizes[2];                       // dist has E elements
    if (E > E_MAX) E = E_MAX;

    k_key<<<2048, 256>>>(anum, eidx, eidx + E, E);
    k_scan<<<1, 1024>>>();
    k_scatter<<<2048, 256>>>(dist, E);
    k_compute<<<NB, 128>>>(emb, out);
}

// round 6
// speedup vs baseline: 4.1181x; 1.0033x over previous
#include <cuda_runtime.h>
#include <cuda_bf16.h>

// Problem constants
#define NUM_HEADS 8
#define NUM_G     50
#define NUM_ELEM  100
#define NB        (NUM_ELEM * NUM_ELEM)   // 10000 distinct (src,dst) pairs
#define E_MAX     1000000

// offsets = linspace(0, 12, 50) -> spacing 12/49 ; std = 12/50
#define RBF_DELTA (12.0 / 49.0)
// k = -0.5/std^2 * log2(e)  (so exp() becomes ex2.approx)
#define RBF_K     (-8.680555555555555 * 1.4426950408889634)
// arg(g) = K*d^2 + MSLOPE*g*d + CQUAD*g^2
#define MSLOPE    (-2.0 * RBF_K * RBF_DELTA)
#define CQUAD     (RBF_K * RBF_DELTA * RBF_DELTA)

// ---- f32x2 packed helpers (sm_100+ PTX) -----------------------------------
__device__ __forceinline__ unsigned long long pk2(float x, float y) {
    unsigned long long r;
    asm("mov.b64 %0, {%1, %2};" : "=l"(r) : "f"(x), "f"(y));
    return r;
}
__device__ __forceinline__ void upk2(unsigned long long v, float& x, float& y) {
    asm("mov.b64 {%0, %1}, %2;" : "=f"(x), "=f"(y) : "l"(v));
}
__device__ __forceinline__ unsigned long long add2(unsigned long long a, unsigned long long b) {
    unsigned long long d;
    asm("add.rn.f32x2 %0, %1, %2;" : "=l"(d) : "l"(a), "l"(b));
    return d;
}
__device__ __forceinline__ unsigned long long fma2(unsigned long long a, unsigned long long b,
                                                   unsigned long long c) {
    unsigned long long d;
    asm("fma.rn.f32x2 %0, %1, %2, %3;" : "=l"(d) : "l"(a), "l"(b), "l"(c));
    return d;
}
__device__ __forceinline__ float ex2(float x) {
    float r;
    asm("ex2.approx.f32 %0, %1;" : "=f"(r) : "f"(x));
    return r;
}

// Scratch (no allocations allowed) -------------------------------------------
// g_hist starts zeroed (device global) and is re-zeroed by k_scan each launch.
__device__ int  g_hist[NB];
__device__ int  g_off[NB + 1];
__device__ int  g_packed[E_MAX];     // (pos_in_bin << 14) | key
__device__ int2 g_sorted2[E_MAX];    // {edge_id, dist_bits} in pair-sorted order

// K1: key + in-bin rank per edge (the ONLY atomic pass) -----------------------
__global__ __launch_bounds__(256) void k_key(
    const int* __restrict__ anum,
    const int* __restrict__ esrc,
    const int* __restrict__ edst,
    int E)
{
    const int S   = gridDim.x * blockDim.x;
    const int idx = blockIdx.x * blockDim.x + threadIdx.x;

#pragma unroll
    for (int u = 0; u < 2; u++) {
        int e = idx + u * S;
        if (e < E) {
            int k = __ldg(anum + __ldg(esrc + e)) * NUM_ELEM
                  + __ldg(anum + __ldg(edst + e));
            int pos = atomicAdd(&g_hist[k], 1);
            g_packed[e] = (pos << 14) | k;
        }
    }
}

// K2: exclusive scan of 10000 bins (single block), then re-zero g_hist --------
__global__ __launch_bounds__(1024) void k_scan()
{
    __shared__ int part[1024];
    const int CHUNK = (NB + 1023) / 1024;       // 10
    int t = threadIdx.x;
    int base = t * CHUNK;

    int cnts[CHUNK];
    int s = 0;
#pragma unroll
    for (int k = 0; k < CHUNK; k++) {
        int i = base + k;
        cnts[k] = (i < NB) ? g_hist[i] : 0;
        s += cnts[k];
    }
    part[t] = s;
    __syncthreads();

    for (int d = 1; d < 1024; d <<= 1) {
        int v = (t >= d) ? part[t - d] : 0;
        __syncthreads();
        part[t] += v;
        __syncthreads();
    }

    int run = part[t] - s;                      // exclusive prefix for chunk
#pragma unroll
    for (int k = 0; k < CHUNK; k++) {
        int i = base + k;
        if (i < NB) {
            g_off[i] = run;
            run += cnts[k];
            g_hist[i] = 0;                      // ready for next launch/replay
        }
    }
    if (t == 1023) g_off[NB] = part[1023];      // total = E
}

// K3: atomic-free scatter of {edge, dist} into pair-sorted order ---------------
__global__ __launch_bounds__(256) void k_scatter(const float* __restrict__ dist, int E)
{
    const int S   = gridDim.x * blockDim.x;
    const int idx = blockIdx.x * blockDim.x + threadIdx.x;

#pragma unroll
    for (int u = 0; u < 2; u++) {
        int e = idx + u * S;
        if (e < E) {
            int p   = g_packed[e];
            int k   = p & 16383;
            int pos = p >> 14;
            g_sorted2[g_off[k] + pos] = make_int2(e, __float_as_int(__ldg(dist + e)));
        }
    }
}

// K4: one block per pair; 2 edges per thread share each weight LDS -------------
__global__ __launch_bounds__(64, 14) void k_compute(
    const float* __restrict__ emb,
    float*       __restrict__ out)
{
    int b   = blockIdx.x;                        // pair key
    int off = g_off[b];
    int cnt = g_off[b + 1] - off;
    if (cnt == 0) return;

    // Ws2[j][h] = { w[h][2j], w[h][2j+1] } : 25 x 8 u64 = 1600 B
    __shared__ __align__(16) unsigned long long Ws2[25 * 8];
    const unsigned long long* W64 =
        (const unsigned long long*)(emb + (size_t)b * (NUM_HEADS * NUM_G));
    for (int i = threadIdx.x; i < 25 * NUM_HEADS; i += 64) {
        int h = i / 25, j = i % 25;              // source u64 index = h*25+j (coalesced)
        Ws2[j * 8 + h] = __ldg(W64 + i);
    }
    __syncthreads();

    for (int base = 0; base < cnt; base += 128) {
        int i0 = base + threadIdx.x;
        int i1 = i0 + 64;
        if (i0 >= cnt) break;                    // i1 active => i0 active
        bool has1 = (i1 < cnt);

        int2  pe0 = __ldg(&g_sorted2[off + i0]);
        int2  pe1 = has1 ? __ldg(&g_sorted2[off + i1]) : pe0;
        float dA  = __int_as_float(pe0.y);
        float dB  = __int_as_float(pe1.y);

        const unsigned long long dA2 = pk2(dA, dA);
        const unsigned long long dB2 = pk2(dB, dB);
        const float tA = (float)RBF_K * dA * dA;
        const float tB = (float)RBF_K * dB * dB;
        const unsigned long long tA2 = pk2(tA, tA);
        const unsigned long long tB2 = pk2(tB, tB);

        unsigned long long accA[NUM_HEADS], accB[NUM_HEADS];
#pragma unroll
        for (int h = 0; h < NUM_HEADS; h++) { accA[h] = 0ull; accB[h] = 0ull; }

#pragma unroll
        for (int j = 0; j < NUM_G / 2; j++) {
            const float g0 = (float)(2 * j), g1 = (float)(2 * j + 1);
            unsigned long long m2 = pk2((float)(MSLOPE * g0), (float)(MSLOPE * g1));
            unsigned long long q2 = pk2((float)(CQUAD * g0 * g0), (float)(CQUAD * g1 * g1));

            unsigned long long argA = fma2(m2, dA2, add2(tA2, q2));
            unsigned long long argB = fma2(m2, dB2, add2(tB2, q2));
            float a0, a1, b0, b1;
            upk2(argA, a0, a1);
            upk2(argB, b0, b1);
            unsigned long long rA = pk2(ex2(a0), ex2(a1));
            unsigned long long rB = pk2(ex2(b0), ex2(b1));

            const ulonglong2* wrow = (const ulonglong2*)&Ws2[j * 8];
            ulonglong2 w01 = wrow[0];
            ulonglong2 w23 = wrow[1];
            ulonglong2 w45 = wrow[2];
            ulonglong2 w67 = wrow[3];
            accA[0] = fma2(w01.x, rA, accA[0]);  accB[0] = fma2(w01.x, rB, accB[0]);
            accA[1] = fma2(w01.y, rA, accA[1]);  accB[1] = fma2(w01.y, rB, accB[1]);
            accA[2] = fma2(w23.x, rA, accA[2]);  accB[2] = fma2(w23.x, rB, accB[2]);
            accA[3] = fma2(w23.y, rA, accA[3]);  accB[3] = fma2(w23.y, rB, accB[3]);
            accA[4] = fma2(w45.x, rA, accA[4]);  accB[4] = fma2(w45.x, rB, accB[4]);
            accA[5] = fma2(w45.y, rA, accA[5]);  accB[5] = fma2(w45.y, rB, accB[5]);
            accA[6] = fma2(w67.x, rA, accA[6]);  accB[6] = fma2(w67.x, rB, accB[6]);
            accA[7] = fma2(w67.y, rA, accA[7]);  accB[7] = fma2(w67.y, rB, accB[7]);
        }

        {
            float r[NUM_HEADS];
#pragma unroll
            for (int h = 0; h < NUM_HEADS; h++) {
                float x0, x1;
                upk2(accA[h], x0, x1);
                r[h] = x0 + x1;
            }
            float4* o = (float4*)(out + (size_t)pe0.x * NUM_HEADS);
            o[0] = make_float4(r[0], r[1], r[2], r[3]);
            o[1] = make_float4(r[4], r[5], r[6], r[7]);
        }
        if (has1) {
            float r[NUM_HEADS];
#pragma unroll
            for (int h = 0; h < NUM_HEADS; h++) {
                float x0, x1;
                upk2(accB[h], x0, x1);
                r[h] = x0 + x1;
            }
            float4* o = (float4*)(out + (size_t)pe1.x * NUM_HEADS);
            o[0] = make_float4(r[0], r[1], r[2], r[3]);
            o[1] = make_float4(r[4], r[5], r[6], r[7]);
        }
    }
}

extern "C" void kernel_launch(void* const* d_in, const int* in_sizes, int n_in,
                              void* d_out, int out_size)
{
    const int*   anum = (const int*)d_in[0];
    const int*   eidx = (const int*)d_in[1];   // [2, E]
    const float* dist = (const float*)d_in[2];
    const float* emb  = (const float*)d_in[3];
    float*       out  = (float*)d_out;

    int E = in_sizes[2];                       // dist has E elements
    if (E > E_MAX) E = E_MAX;

    k_key<<<2048, 256>>>(anum, eidx, eidx + E, E);
    k_scan<<<1, 1024>>>();
    k_scatter<<<2048, 256>>>(dist, E);
    k_compute<<<NB, 64>>>(emb, out);
}

// round 7
// speedup vs baseline: 5.1836x; 1.2587x over previous
#include <cuda_runtime.h>
#include <cuda_bf16.h>

// Problem constants
#define NUM_HEADS 8
#define NUM_G     50
#define NUM_ELEM  100
#define NB        (NUM_ELEM * NUM_ELEM)   // 10000 distinct (src,dst) pairs
#define E_MAX     1000000
#define CAP       256                     // slots per bin (max bin ~145 for this E)
#define OVF_MAX   8192

// offsets = linspace(0, 12, 50) -> spacing 12/49 ; std = 12/50
#define RBF_DELTA (12.0 / 49.0)
// k = -0.5/std^2 * log2(e)  (so exp() becomes ex2.approx)
#define RBF_K     (-8.680555555555555 * 1.4426950408889634)
// arg(g) = K*d^2 + MSLOPE*g*d + CQUAD*g^2
#define MSLOPE    (-2.0 * RBF_K * RBF_DELTA)
#define CQUAD     (RBF_K * RBF_DELTA * RBF_DELTA)

// ---- f32x2 packed helpers (sm_100+ PTX) -----------------------------------
__device__ __forceinline__ unsigned long long pk2(float x, float y) {
    unsigned long long r;
    asm("mov.b64 %0, {%1, %2};" : "=l"(r) : "f"(x), "f"(y));
    return r;
}
__device__ __forceinline__ void upk2(unsigned long long v, float& x, float& y) {
    asm("mov.b64 {%0, %1}, %2;" : "=f"(x), "=f"(y) : "l"(v));
}
__device__ __forceinline__ unsigned long long add2(unsigned long long a, unsigned long long b) {
    unsigned long long d;
    asm("add.rn.f32x2 %0, %1, %2;" : "=l"(d) : "l"(a), "l"(b));
    return d;
}
__device__ __forceinline__ unsigned long long fma2(unsigned long long a, unsigned long long b,
                                                   unsigned long long c) {
    unsigned long long d;
    asm("fma.rn.f32x2 %0, %1, %2, %3;" : "=l"(d) : "l"(a), "l"(b), "l"(c));
    return d;
}
__device__ __forceinline__ float ex2(float x) {
    float r;
    asm("ex2.approx.f32 %0, %1;" : "=f"(r) : "f"(x));
    return r;
}

// Scratch (no allocations allowed) -------------------------------------------
// g_hist starts zeroed (device global); k_compute re-zeros its bin each launch.
__device__ int  g_hist[NB];
__device__ int2 g_bins[NB * CAP];    // {edge_id, dist_bits}, bin-bucketed (20 MB)
__device__ int  g_ovf_cnt;
__device__ int  g_ovf[OVF_MAX];

// K1: key + rank + direct bucket store (the only binning pass) ----------------
__global__ __launch_bounds__(256) void k_key_direct(
    const int*   __restrict__ anum,
    const int*   __restrict__ esrc,
    const int*   __restrict__ edst,
    const float* __restrict__ dist,
    int E)
{
    const int S   = gridDim.x * blockDim.x;
    const int idx = blockIdx.x * blockDim.x + threadIdx.x;

#pragma unroll
    for (int u = 0; u < 2; u++) {
        int e = idx + u * S;
        if (e < E) {
            int k = __ldg(anum + __ldg(esrc + e)) * NUM_ELEM
                  + __ldg(anum + __ldg(edst + e));
            float d = __ldg(dist + e);
            int pos = atomicAdd(&g_hist[k], 1);
            if (pos < CAP) {
                g_bins[k * CAP + pos] = make_int2(e, __float_as_int(d));
            } else {
                int o = atomicAdd(&g_ovf_cnt, 1);
                if (o < OVF_MAX) g_ovf[o] = e;
            }
        }
    }
}

// K2: one block per pair; 2 edges per thread share each weight LDS -------------
__global__ __launch_bounds__(64, 14) void k_compute(
    const float* __restrict__ emb,
    float*       __restrict__ out)
{
    int b   = blockIdx.x;                        // pair key
    int cnt = g_hist[b];                         // all threads read BEFORE the sync
    if (cnt > CAP) cnt = CAP;
    const int2* bin = &g_bins[b * CAP];

    // Ws2[j][h] = { w[h][2j], w[h][2j+1] } : 25 x 8 u64 = 1600 B
    __shared__ __align__(16) unsigned long long Ws2[25 * 8];
    if (cnt > 0) {
        const unsigned long long* W64 =
            (const unsigned long long*)(emb + (size_t)b * (NUM_HEADS * NUM_G));
        for (int i = threadIdx.x; i < 25 * NUM_HEADS; i += 64) {
            int h = i / 25, j = i % 25;          // source u64 index = h*25+j (coalesced)
            Ws2[j * 8 + h] = __ldg(W64 + i);
        }
    }
    __syncthreads();
    if (threadIdx.x == 0) g_hist[b] = 0;         // reset for next launch/replay
    if (cnt == 0) return;

    for (int base = 0; base < cnt; base += 128) {
        int i0 = base + threadIdx.x;
        int i1 = i0 + 64;
        if (i0 >= cnt) break;                    // i1 active => i0 active
        bool has1 = (i1 < cnt);

        int2  pe0 = __ldg(&bin[i0]);
        int2  pe1 = has1 ? __ldg(&bin[i1]) : pe0;
        float dA  = __int_as_float(pe0.y);
        float dB  = __int_as_float(pe1.y);

        const unsigned long long dA2 = pk2(dA, dA);
        const unsigned long long dB2 = pk2(dB, dB);
        const float tA = (float)RBF_K * dA * dA;
        const float tB = (float)RBF_K * dB * dB;
        const unsigned long long tA2 = pk2(tA, tA);
        const unsigned long long tB2 = pk2(tB, tB);

        unsigned long long accA[NUM_HEADS], accB[NUM_HEADS];
#pragma unroll
        for (int h = 0; h < NUM_HEADS; h++) { accA[h] = 0ull; accB[h] = 0ull; }

#pragma unroll
        for (int j = 0; j < NUM_G / 2; j++) {
            const float g0 = (float)(2 * j), g1 = (float)(2 * j + 1);
            unsigned long long m2 = pk2((float)(MSLOPE * g0), (float)(MSLOPE * g1));
            unsigned long long q2 = pk2((float)(CQUAD * g0 * g0), (float)(CQUAD * g1 * g1));

            unsigned long long argA = fma2(m2, dA2, add2(tA2, q2));
            unsigned long long argB = fma2(m2, dB2, add2(tB2, q2));
            float a0, a1, b0, b1;
            upk2(argA, a0, a1);
            upk2(argB, b0, b1);
            unsigned long long rA = pk2(ex2(a0), ex2(a1));
            unsigned long long rB = pk2(ex2(b0), ex2(b1));

            const ulonglong2* wrow = (const ulonglong2*)&Ws2[j * 8];
            ulonglong2 w01 = wrow[0];
            ulonglong2 w23 = wrow[1];
            ulonglong2 w45 = wrow[2];
            ulonglong2 w67 = wrow[3];
            accA[0] = fma2(w01.x, rA, accA[0]);  accB[0] = fma2(w01.x, rB, accB[0]);
            accA[1] = fma2(w01.y, rA, accA[1]);  accB[1] = fma2(w01.y, rB, accB[1]);
            accA[2] = fma2(w23.x, rA, accA[2]);  accB[2] = fma2(w23.x, rB, accB[2]);
            accA[3] = fma2(w23.y, rA, accA[3]);  accB[3] = fma2(w23.y, rB, accB[3]);
            accA[4] = fma2(w45.x, rA, accA[4]);  accB[4] = fma2(w45.x, rB, accB[4]);
            accA[5] = fma2(w45.y, rA, accA[5]);  accB[5] = fma2(w45.y, rB, accB[5]);
            accA[6] = fma2(w67.x, rA, accA[6]);  accB[6] = fma2(w67.x, rB, accB[6]);
            accA[7] = fma2(w67.y, rA, accA[7]);  accB[7] = fma2(w67.y, rB, accB[7]);
        }

        {
            float r[NUM_HEADS];
#pragma unroll
            for (int h = 0; h < NUM_HEADS; h++) {
                float x0, x1;
                upk2(accA[h], x0, x1);
                r[h] = x0 + x1;
            }
            float4* o = (float4*)(out + (size_t)pe0.x * NUM_HEADS);
            o[0] = make_float4(r[0], r[1], r[2], r[3]);
            o[1] = make_float4(r[4], r[5], r[6], r[7]);
        }
        if (has1) {
            float r[NUM_HEADS];
#pragma unroll
            for (int h = 0; h < NUM_HEADS; h++) {
                float x0, x1;
                upk2(accB[h], x0, x1);
                r[h] = x0 + x1;
            }
            float4* o = (float4*)(out + (size_t)pe1.x * NUM_HEADS);
            o[0] = make_float4(r[0], r[1], r[2], r[3]);
            o[1] = make_float4(r[4], r[5], r[6], r[7]);
        }
    }
}

// K3: overflow cleanup (expected count 0); single block so the counter reset
// is safely ordered after all processing.
__global__ __launch_bounds__(256) void k_ovf(
    const int*   __restrict__ anum,
    const int*   __restrict__ esrc,
    const int*   __restrict__ edst,
    const float* __restrict__ dist,
    const float* __restrict__ emb,
    float*       __restrict__ out)
{
    int n = g_ovf_cnt;
    if (n > OVF_MAX) n = OVF_MAX;
    for (int i = threadIdx.x; i < n; i += 256) {
        int e = g_ovf[i];
        int k = __ldg(anum + __ldg(esrc + e)) * NUM_ELEM
              + __ldg(anum + __ldg(edst + e));
        float d = __ldg(dist + e);
        const float* W = emb + (size_t)k * (NUM_HEADS * NUM_G);
        float t = (float)RBF_K * d * d;
        float rbf[NUM_G];
#pragma unroll
        for (int g = 0; g < NUM_G; g++)
            rbf[g] = ex2(t + (float)(MSLOPE * g) * d + (float)(CQUAD * g * g));
        for (int h = 0; h < NUM_HEADS; h++) {
            float a = 0.f;
#pragma unroll
            for (int g = 0; g < NUM_G; g++)
                a = fmaf(__ldg(W + h * NUM_G + g), rbf[g], a);
            out[(size_t)e * NUM_HEADS + h] = a;
        }
    }
    __syncthreads();
    if (threadIdx.x == 0) g_ovf_cnt = 0;        // reset for next launch/replay
}

extern "C" void kernel_launch(void* const* d_in, const int* in_sizes, int n_in,
                              void* d_out, int out_size)
{
    const int*   anum = (const int*)d_in[0];
    const int*   eidx = (const int*)d_in[1];   // [2, E]
    const float* dist = (const float*)d_in[2];
    const float* emb  = (const float*)d_in[3];
    float*       out  = (float*)d_out;

    int E = in_sizes[2];                       // dist has E elements
    if (E > E_MAX) E = E_MAX;

    k_key_direct<<<2048, 256>>>(anum, eidx, eidx + E, dist, E);
    k_compute<<<NB, 64>>>(emb, out);
    k_ovf<<<1, 256>>>(anum, eidx, eidx + E, dist, emb, out);
}

// round 8
// speedup vs baseline: 5.1863x; 1.0005x over previous
#include <cuda_runtime.h>
#include <cuda_bf16.h>

// Problem constants
#define NUM_HEADS 8
#define NUM_G     50
#define NUM_ELEM  100
#define NB        (NUM_ELEM * NUM_ELEM)   // 10000 distinct (src,dst) pairs
#define E_MAX     1000000
#define CAP       256                     // slots per bin (max bin ~145 for this E)
#define OVF_MAX   8192

// offsets = linspace(0, 12, 50) -> spacing 12/49 ; std = 12/50
#define RBF_DELTA (12.0 / 49.0)
// k = -0.5/std^2 * log2(e)  (so exp() becomes ex2.approx)
#define RBF_K     (-8.680555555555555 * 1.4426950408889634)
// arg(g) = K*d^2 + MSLOPE*g*d + CQUAD*g^2
#define MSLOPE    (-2.0 * RBF_K * RBF_DELTA)
#define CQUAD     (RBF_K * RBF_DELTA * RBF_DELTA)

// ---- f32x2 packed helpers (sm_100+ PTX) -----------------------------------
__device__ __forceinline__ unsigned long long pk2(float x, float y) {
    unsigned long long r;
    asm("mov.b64 %0, {%1, %2};" : "=l"(r) : "f"(x), "f"(y));
    return r;
}
__device__ __forceinline__ void upk2(unsigned long long v, float& x, float& y) {
    asm("mov.b64 {%0, %1}, %2;" : "=f"(x), "=f"(y) : "l"(v));
}
__device__ __forceinline__ unsigned long long add2(unsigned long long a, unsigned long long b) {
    unsigned long long d;
    asm("add.rn.f32x2 %0, %1, %2;" : "=l"(d) : "l"(a), "l"(b));
    return d;
}
__device__ __forceinline__ unsigned long long fma2(unsigned long long a, unsigned long long b,
                                                   unsigned long long c) {
    unsigned long long d;
    asm("fma.rn.f32x2 %0, %1, %2, %3;" : "=l"(d) : "l"(a), "l"(b), "l"(c));
    return d;
}
__device__ __forceinline__ float ex2(float x) {
    float r;
    asm("ex2.approx.f32 %0, %1;" : "=f"(r) : "f"(x));
    return r;
}

// Scratch (no allocations allowed) -------------------------------------------
// g_hist starts zeroed (device global); k_compute re-zeros its bin each launch.
__device__ int  g_hist[NB];
__device__ int2 g_bins[NB * CAP];    // {edge_id, dist_bits}, bin-bucketed (20 MB)
__device__ int  g_ovf_cnt;
__device__ int  g_ovf[OVF_MAX];

// K1: key + rank + direct bucket store (the only binning pass) ----------------
__global__ __launch_bounds__(256) void k_key_direct(
    const int*   __restrict__ anum,
    const int*   __restrict__ esrc,
    const int*   __restrict__ edst,
    const float* __restrict__ dist,
    int E)
{
    const int S   = gridDim.x * blockDim.x;
    const int idx = blockIdx.x * blockDim.x + threadIdx.x;

#pragma unroll
    for (int u = 0; u < 2; u++) {
        int e = idx + u * S;
        if (e < E) {
            int k = __ldg(anum + __ldg(esrc + e)) * NUM_ELEM
                  + __ldg(anum + __ldg(edst + e));
            float d = __ldg(dist + e);
            int pos = atomicAdd(&g_hist[k], 1);
            if (pos < CAP) {
                g_bins[k * CAP + pos] = make_int2(e, __float_as_int(d));
            } else {
                int o = atomicAdd(&g_ovf_cnt, 1);
                if (o < OVF_MAX) g_ovf[o] = e;
            }
        }
    }
}

// K2: one block per pair; 2 edges per thread share each weight LDS -------------
__global__ __launch_bounds__(64, 14) void k_compute(
    const float* __restrict__ emb,
    float*       __restrict__ out)
{
    int b   = blockIdx.x;                        // pair key
    int cnt = g_hist[b];                         // all threads read BEFORE the sync
    if (cnt > CAP) cnt = CAP;
    const int2* bin = &g_bins[b * CAP];

    // Ws2[j][h] = { w[h][2j], w[h][2j+1] } : 25 x 8 u64 = 1600 B
    __shared__ __align__(16) unsigned long long Ws2[25 * 8];
    if (cnt > 0) {
        const unsigned long long* W64 =
            (const unsigned long long*)(emb + (size_t)b * (NUM_HEADS * NUM_G));
        for (int i = threadIdx.x; i < 25 * NUM_HEADS; i += 64) {
            int h = i / 25, j = i % 25;          // source u64 index = h*25+j (coalesced)
            Ws2[j * 8 + h] = __ldg(W64 + i);
        }
    }
    __syncthreads();
    if (threadIdx.x == 0) g_hist[b] = 0;         // reset for next launch/replay
    if (cnt == 0) return;

    for (int base = 0; base < cnt; base += 128) {
        int i0 = base + threadIdx.x;
        int i1 = i0 + 64;
        if (i0 >= cnt) break;                    // i1 active => i0 active
        bool has1 = (i1 < cnt);

        int2  pe0 = __ldg(&bin[i0]);
        int2  pe1 = has1 ? __ldg(&bin[i1]) : pe0;
        float dA  = __int_as_float(pe0.y);
        float dB  = __int_as_float(pe1.y);

        const unsigned long long dA2 = pk2(dA, dA);
        const unsigned long long dB2 = pk2(dB, dB);
        const float tA = (float)RBF_K * dA * dA;
        const float tB = (float)RBF_K * dB * dB;
        const unsigned long long tA2 = pk2(tA, tA);
        const unsigned long long tB2 = pk2(tB, tB);

        unsigned long long accA[NUM_HEADS], accB[NUM_HEADS];
#pragma unroll
        for (int h = 0; h < NUM_HEADS; h++) { accA[h] = 0ull; accB[h] = 0ull; }

#pragma unroll
        for (int j = 0; j < NUM_G / 2; j++) {
            const float g0 = (float)(2 * j), g1 = (float)(2 * j + 1);
            unsigned long long m2 = pk2((float)(MSLOPE * g0), (float)(MSLOPE * g1));
            unsigned long long q2 = pk2((float)(CQUAD * g0 * g0), (float)(CQUAD * g1 * g1));

            unsigned long long argA = fma2(m2, dA2, add2(tA2, q2));
            unsigned long long argB = fma2(m2, dB2, add2(tB2, q2));
            float a0, a1, b0, b1;
            upk2(argA, a0, a1);
            upk2(argB, b0, b1);
            unsigned long long rA = pk2(ex2(a0), ex2(a1));
            unsigned long long rB = pk2(ex2(b0), ex2(b1));

            const ulonglong2* wrow = (const ulonglong2*)&Ws2[j * 8];
            ulonglong2 w01 = wrow[0];
            ulonglong2 w23 = wrow[1];
            ulonglong2 w45 = wrow[2];
            ulonglong2 w67 = wrow[3];
            accA[0] = fma2(w01.x, rA, accA[0]);  accB[0] = fma2(w01.x, rB, accB[0]);
            accA[1] = fma2(w01.y, rA, accA[1]);  accB[1] = fma2(w01.y, rB, accB[1]);
            accA[2] = fma2(w23.x, rA, accA[2]);  accB[2] = fma2(w23.x, rB, accB[2]);
            accA[3] = fma2(w23.y, rA, accA[3]);  accB[3] = fma2(w23.y, rB, accB[3]);
            accA[4] = fma2(w45.x, rA, accA[4]);  accB[4] = fma2(w45.x, rB, accB[4]);
            accA[5] = fma2(w45.y, rA, accA[5]);  accB[5] = fma2(w45.y, rB, accB[5]);
            accA[6] = fma2(w67.x, rA, accA[6]);  accB[6] = fma2(w67.x, rB, accB[6]);
            accA[7] = fma2(w67.y, rA, accA[7]);  accB[7] = fma2(w67.y, rB, accB[7]);
        }

        {
            float r[NUM_HEADS];
#pragma unroll
            for (int h = 0; h < NUM_HEADS; h++) {
                float x0, x1;
                upk2(accA[h], x0, x1);
                r[h] = x0 + x1;
            }
            float4* o = (float4*)(out + (size_t)pe0.x * NUM_HEADS);
            o[0] = make_float4(r[0], r[1], r[2], r[3]);
            o[1] = make_float4(r[4], r[5], r[6], r[7]);
        }
        if (has1) {
            float r[NUM_HEADS];
#pragma unroll
            for (int h = 0; h < NUM_HEADS; h++) {
                float x0, x1;
                upk2(accB[h], x0, x1);
                r[h] = x0 + x1;
            }
            float4* o = (float4*)(out + (size_t)pe1.x * NUM_HEADS);
            o[0] = make_float4(r[0], r[1], r[2], r[3]);
            o[1] = make_float4(r[4], r[5], r[6], r[7]);
        }
    }
}

// K3: overflow cleanup (expected count 0); single block so the counter reset
// is safely ordered after all processing.
__global__ __launch_bounds__(256) void k_ovf(
    const int*   __restrict__ anum,
    const int*   __restrict__ esrc,
    const int*   __restrict__ edst,
    const float* __restrict__ dist,
    const float* __restrict__ emb,
    float*       __restrict__ out)
{
    int n = g_ovf_cnt;
    if (n > OVF_MAX) n = OVF_MAX;
    for (int i = threadIdx.x; i < n; i += 256) {
        int e = g_ovf[i];
        int k = __ldg(anum + __ldg(esrc + e)) * NUM_ELEM
              + __ldg(anum + __ldg(edst + e));
        float d = __ldg(dist + e);
        const float* W = emb + (size_t)k * (NUM_HEADS * NUM_G);
        float t = (float)RBF_K * d * d;
        float rbf[NUM_G];
#pragma unroll
        for (int g = 0; g < NUM_G; g++)
            rbf[g] = ex2(t + (float)(MSLOPE * g) * d + (float)(CQUAD * g * g));
        for (int h = 0; h < NUM_HEADS; h++) {
            float a = 0.f;
#pragma unroll
            for (int g = 0; g < NUM_G; g++)
                a = fmaf(__ldg(W + h * NUM_G + g), rbf[g], a);
            out[(size_t)e * NUM_HEADS + h] = a;
        }
    }
    __syncthreads();
    if (threadIdx.x == 0) g_ovf_cnt = 0;        // reset for next launch/replay
}

extern "C" void kernel_launch(void* const* d_in, const int* in_sizes, int n_in,
                              void* d_out, int out_size)
{
    const int*   anum = (const int*)d_in[0];
    const int*   eidx = (const int*)d_in[1];   // [2, E]
    const float* dist = (const float*)d_in[2];
    const float* emb  = (const float*)d_in[3];
    float*       out  = (float*)d_out;

    int E = in_sizes[2];                       // dist has E elements
    if (E > E_MAX) E = E_MAX;

    k_key_direct<<<2048, 256>>>(anum, eidx, eidx + E, dist, E);
    k_compute<<<NB, 64>>>(emb, out);
    k_ovf<<<1, 256>>>(anum, eidx, eidx + E, dist, emb, out);
}

// round 9
// speedup vs baseline: 5.7781x; 1.1141x over previous
#include <cuda_runtime.h>
#include <cuda_bf16.h>

// Problem constants
#define NUM_HEADS 8
#define NUM_G     50
#define NUM_ELEM  100
#define NB        (NUM_ELEM * NUM_ELEM)   // 10000 distinct (src,dst) pairs
#define E_MAX     1000000
#define NREP      4                       // counter replicas per bin
#define RCAP      64                      // slots per replica (4*64 = 256 per bin)
#define OVF_MAX   8192

// offsets = linspace(0, 12, 50) -> spacing 12/49 ; std = 12/50
#define RBF_DELTA (12.0 / 49.0)
// k = -0.5/std^2 * log2(e)  (so exp() becomes ex2.approx)
#define RBF_K     (-8.680555555555555 * 1.4426950408889634)
// arg(g) = K*d^2 + MSLOPE*g*d + CQUAD*g^2
#define MSLOPE    (-2.0 * RBF_K * RBF_DELTA)
#define CQUAD     (RBF_K * RBF_DELTA * RBF_DELTA)

// ---- f32x2 packed helpers (sm_100+ PTX) -----------------------------------
__device__ __forceinline__ unsigned long long pk2(float x, float y) {
    unsigned long long r;
    asm("mov.b64 %0, {%1, %2};" : "=l"(r) : "f"(x), "f"(y));
    return r;
}
__device__ __forceinline__ void upk2(unsigned long long v, float& x, float& y) {
    asm("mov.b64 {%0, %1}, %2;" : "=f"(x), "=f"(y) : "l"(v));
}
__device__ __forceinline__ unsigned long long add2(unsigned long long a, unsigned long long b) {
    unsigned long long d;
    asm("add.rn.f32x2 %0, %1, %2;" : "=l"(d) : "l"(a), "l"(b));
    return d;
}
__device__ __forceinline__ unsigned long long fma2(unsigned long long a, unsigned long long b,
                                                   unsigned long long c) {
    unsigned long long d;
    asm("fma.rn.f32x2 %0, %1, %2, %3;" : "=l"(d) : "l"(a), "l"(b), "l"(c));
    return d;
}
__device__ __forceinline__ float ex2(float x) {
    float r;
    asm("ex2.approx.f32 %0, %1;" : "=f"(r) : "f"(x));
    return r;
}

// Scratch (no allocations allowed) -------------------------------------------
// g_cnt4 starts zeroed (device global); k_compute re-zeros its bin each launch.
__device__ int4 g_cnt4[NB];          // 4 replica counters per bin
__device__ int2 g_bins[NB * NREP * RCAP];  // {edge_id, dist_bits} (20 MB)
__device__ int  g_ovf_cnt;
__device__ int  g_ovf[OVF_MAX];

// K1: key + replica rank + direct bucket store --------------------------------
__global__ __launch_bounds__(256) void k_key_direct(
    const int*   __restrict__ anum,
    const int*   __restrict__ esrc,
    const int*   __restrict__ edst,
    const float* __restrict__ dist,
    int E)
{
    const int S   = gridDim.x * blockDim.x;
    const int idx = blockIdx.x * blockDim.x + threadIdx.x;

#pragma unroll
    for (int u = 0; u < 2; u++) {
        int e = idx + u * S;
        if (e < E) {
            int k = __ldg(anum + __ldg(esrc + e)) * NUM_ELEM
                  + __ldg(anum + __ldg(edst + e));
            float d = __ldg(dist + e);
            int r = e & (NREP - 1);              // replica: spreads within a warp
            int pos = atomicAdd(&((int*)&g_cnt4[k])[r], 1);
            if (pos < RCAP) {
                g_bins[(k * NREP + r) * RCAP + pos] = make_int2(e, __float_as_int(d));
            } else {
                int o = atomicAdd(&g_ovf_cnt, 1);
                if (o < OVF_MAX) g_ovf[o] = e;
            }
        }
    }
}

// K2: one block per pair; walks the 4 replica chunks; 2 edges per thread -------
__global__ __launch_bounds__(64, 14) void k_compute(
    const float* __restrict__ emb,
    float*       __restrict__ out)
{
    int b = blockIdx.x;                          // pair key
    int4 c4 = g_cnt4[b];                         // all threads read BEFORE reset
    int c0 = min(c4.x, RCAP), c1 = min(c4.y, RCAP);
    int c2 = min(c4.z, RCAP), c3 = min(c4.w, RCAP);
    int s0 = c0, s1 = s0 + c1, s2 = s1 + c2;
    int cnt = s2 + c3;
    const int2* bin = &g_bins[b * (NREP * RCAP)];

    // Ws2[j][h] = { w[h][2j], w[h][2j+1] } : 25 x 8 u64 = 1600 B
    __shared__ __align__(16) unsigned long long Ws2[25 * 8];
    if (cnt > 0) {
        const unsigned long long* W64 =
            (const unsigned long long*)(emb + (size_t)b * (NUM_HEADS * NUM_G));
        for (int i = threadIdx.x; i < 25 * NUM_HEADS; i += 64) {
            int h = i / 25, j = i % 25;          // source u64 index = h*25+j (coalesced)
            Ws2[j * 8 + h] = __ldg(W64 + i);
        }
    }
    __syncthreads();
    if (threadIdx.x == 0) g_cnt4[b] = make_int4(0, 0, 0, 0);  // next launch/replay
    if (cnt == 0) return;

    for (int base = 0; base < cnt; base += 128) {
        int i0 = base + threadIdx.x;
        int i1 = i0 + 64;
        if (i0 >= cnt) break;                    // i1 active => i0 active
        bool has1 = (i1 < cnt);

        // map logical index -> replica chunk slot
        int a0 = (i0 < s0) ? i0
               : (i0 < s1) ? (RCAP     + i0 - s0)
               : (i0 < s2) ? (2 * RCAP + i0 - s1)
               :             (3 * RCAP + i0 - s2);
        int j1 = has1 ? i1 : i0;
        int a1 = (j1 < s0) ? j1
               : (j1 < s1) ? (RCAP     + j1 - s0)
               : (j1 < s2) ? (2 * RCAP + j1 - s1)
               :             (3 * RCAP + j1 - s2);

        int2  pe0 = __ldg(&bin[a0]);
        int2  pe1 = __ldg(&bin[a1]);
        float dA  = __int_as_float(pe0.y);
        float dB  = __int_as_float(pe1.y);

        const unsigned long long dA2 = pk2(dA, dA);
        const unsigned long long dB2 = pk2(dB, dB);
        const float tA = (float)RBF_K * dA * dA;
        const float tB = (float)RBF_K * dB * dB;
        const unsigned long long tA2 = pk2(tA, tA);
        const unsigned long long tB2 = pk2(tB, tB);

        unsigned long long accA[NUM_HEADS], accB[NUM_HEADS];
#pragma unroll
        for (int h = 0; h < NUM_HEADS; h++) { accA[h] = 0ull; accB[h] = 0ull; }

#pragma unroll
        for (int j = 0; j < NUM_G / 2; j++) {
            const float g0 = (float)(2 * j), g1 = (float)(2 * j + 1);
            unsigned long long m2 = pk2((float)(MSLOPE * g0), (float)(MSLOPE * g1));
            unsigned long long q2 = pk2((float)(CQUAD * g0 * g0), (float)(CQUAD * g1 * g1));

            unsigned long long argA = fma2(m2, dA2, add2(tA2, q2));
            unsigned long long argB = fma2(m2, dB2, add2(tB2, q2));
            float a0f, a1f, b0f, b1f;
            upk2(argA, a0f, a1f);
            upk2(argB, b0f, b1f);
            unsigned long long rA = pk2(ex2(a0f), ex2(a1f));
            unsigned long long rB = pk2(ex2(b0f), ex2(b1f));

            const ulonglong2* wrow = (const ulonglong2*)&Ws2[j * 8];
            ulonglong2 w01 = wrow[0];
            ulonglong2 w23 = wrow[1];
            ulonglong2 w45 = wrow[2];
            ulonglong2 w67 = wrow[3];
            accA[0] = fma2(w01.x, rA, accA[0]);  accB[0] = fma2(w01.x, rB, accB[0]);
            accA[1] = fma2(w01.y, rA, accA[1]);  accB[1] = fma2(w01.y, rB, accB[1]);
            accA[2] = fma2(w23.x, rA, accA[2]);  accB[2] = fma2(w23.x, rB, accB[2]);
            accA[3] = fma2(w23.y, rA, accA[3]);  accB[3] = fma2(w23.y, rB, accB[3]);
            accA[4] = fma2(w45.x, rA, accA[4]);  accB[4] = fma2(w45.x, rB, accB[4]);
            accA[5] = fma2(w45.y, rA, accA[5]);  accB[5] = fma2(w45.y, rB, accB[5]);
            accA[6] = fma2(w67.x, rA, accA[6]);  accB[6] = fma2(w67.x, rB, accB[6]);
            accA[7] = fma2(w67.y, rA, accA[7]);  accB[7] = fma2(w67.y, rB, accB[7]);
        }

        {
            float r[NUM_HEADS];
#pragma unroll
            for (int h = 0; h < NUM_HEADS; h++) {
                float x0, x1;
                upk2(accA[h], x0, x1);
                r[h] = x0 + x1;
            }
            float4* o = (float4*)(out + (size_t)pe0.x * NUM_HEADS);
            o[0] = make_float4(r[0], r[1], r[2], r[3]);
            o[1] = make_float4(r[4], r[5], r[6], r[7]);
        }
        if (has1) {
            float r[NUM_HEADS];
#pragma unroll
            for (int h = 0; h < NUM_HEADS; h++) {
                float x0, x1;
                upk2(accB[h], x0, x1);
                r[h] = x0 + x1;
            }
            float4* o = (float4*)(out + (size_t)pe1.x * NUM_HEADS);
            o[0] = make_float4(r[0], r[1], r[2], r[3]);
            o[1] = make_float4(r[4], r[5], r[6], r[7]);
        }
    }
}

// K3: overflow cleanup (expected count 0); single block so the counter reset
// is safely ordered after all processing.
__global__ __launch_bounds__(256) void k_ovf(
    const int*   __restrict__ anum,
    const int*   __restrict__ esrc,
    const int*   __restrict__ edst,
    const float* __restrict__ dist,
    const float* __restrict__ emb,
    float*       __restrict__ out)
{
    int n = g_ovf_cnt;
    if (n > OVF_MAX) n = OVF_MAX;
    for (int i = threadIdx.x; i < n; i += 256) {
        int e = g_ovf[i];
        int k = __ldg(anum + __ldg(esrc + e)) * NUM_ELEM
              + __ldg(anum + __ldg(edst + e));
        float d = __ldg(dist + e);
        const float* W = emb + (size_t)k * (NUM_HEADS * NUM_G);
        float t = (float)RBF_K * d * d;
        float rbf[NUM_G];
#pragma unroll
        for (int g = 0; g < NUM_G; g++)
            rbf[g] = ex2(t + (float)(MSLOPE * g) * d + (float)(CQUAD * g * g));
        for (int h = 0; h < NUM_HEADS; h++) {
            float a = 0.f;
#pragma unroll
            for (int g = 0; g < NUM_G; g++)
                a = fmaf(__ldg(W + h * NUM_G + g), rbf[g], a);
            out[(size_t)e * NUM_HEADS + h] = a;
        }
    }
    __syncthreads();
    if (threadIdx.x == 0) g_ovf_cnt = 0;        // reset for next launch/replay
}

extern "C" void kernel_launch(void* const* d_in, const int* in_sizes, int n_in,
                              void* d_out, int out_size)
{
    const int*   anum = (const int*)d_in[0];
    const int*   eidx = (const int*)d_in[1];   // [2, E]
    const float* dist = (const float*)d_in[2];
    const float* emb  = (const float*)d_in[3];
    float*       out  = (float*)d_out;

    int E = in_sizes[2];                       // dist has E elements
    if (E > E_MAX) E = E_MAX;

    k_key_direct<<<2048, 256>>>(anum, eidx, eidx + E, dist, E);
    k_compute<<<NB, 64>>>(emb, out);
    k_ovf<<<1, 256>>>(anum, eidx, eidx + E, dist, emb, out);
}